// round 4
// baseline (speedup 1.0000x reference)
#include <cuda_runtime.h>
#include <cstdint>

// out[b] = a[b] @ x[b] : a [8,4096,4096] f32, x [8,4096,32] f32, out [8,4096,32] f32
// Round 4: round-2 skeleton (no K-split, direct stores) + pre-permuted/pre-rounded X
// (B-frags via LDS.128) + 5-stage cp.async pipeline.

#define DEV __device__ __forceinline__

constexpr int Bsz = 8;
constexpr int Nn  = 4096;
constexpr int Dd  = 32;
constexpr int Kk  = 4096;

constexpr int BM  = 64;
constexpr int BK  = 32;
constexpr int NIT = Kk / BK;   // 128
constexpr int THREADS = 128;
constexpr int STAGES = 5;

constexpr int A_STAGE_F = BM * BK;       // 2048 floats
constexpr int X_STAGE_F = BK * Dd;       // 1024 floats
constexpr int A_STAGE_B = A_STAGE_F * 4; // 8192 B
constexpr int X_STAGE_B = X_STAGE_F * 4; // 4096 B
constexpr int SMEM_BYTES = STAGES * (A_STAGE_B + X_STAGE_B); // 61440 B

// Permuted, tf32-rounded X: [b][kb(128)][ks(4)][lane(32)][8 floats], bank-swizzled.
__device__ float g_xperm[Bsz * (Kk / BK) * X_STAGE_F];

DEV uint32_t cvta_s(const void* p) { return (uint32_t)__cvta_generic_to_shared(p); }
DEV void cp16(uint32_t dst, const void* src) {
    asm volatile("cp.async.cg.shared.global [%0], [%1], 16;\n" :: "r"(dst), "l"(src));
}
DEV void cp_commit() { asm volatile("cp.async.commit_group;\n" ::: "memory"); }

#define MMA_TF32(C, A0, A1, A2, A3, B0, B1)                                    \
    asm volatile(                                                              \
        "mma.sync.aligned.m16n8k8.row.col.f32.tf32.tf32.f32 "                  \
        "{%0,%1,%2,%3}, {%4,%5,%6,%7}, {%8,%9}, {%0,%1,%2,%3};\n"              \
        : "+f"(C[0]), "+f"(C[1]), "+f"(C[2]), "+f"(C[3])                       \
        : "r"(A0), "r"(A1), "r"(A2), "r"(A3), "r"(B0), "r"(B1))

// ---------------- permute + rna-round X (validated in round 3) ----------------
__global__ void permute_x_kernel(const float* __restrict__ x) {
    int o = blockIdx.x * blockDim.x + threadIdx.x;
    int w    = o & 3;
    int c    = (o >> 2) & 1;
    int lane = (o >> 3) & 31;
    int ks   = (o >> 8) & 3;
    int kb   = (o >> 10) & 127;
    int b    = o >> 17;
    int s = (lane >> 2) & 1;
    int h = c ^ s;
    int j = h * 4 + w;
    int tig = lane & 3, gid = lane >> 2;
    int k = kb * 32 + ks * 8 + tig + 4 * (j & 1);
    int d = (j >> 1) * 8 + gid;
    float v = x[((size_t)b * Kk + k) * Dd + d];
    uint32_t t;
    asm("cvt.rna.tf32.f32 %0, %1;" : "=r"(t) : "f"(v));
    g_xperm[o] = __uint_as_float(t);
}

// ---------------- main GEMM ----------------
__global__ __launch_bounds__(THREADS)
void gsum_tf32_kernel(const float* __restrict__ a, float* __restrict__ out)
{
    extern __shared__ float smem[];
    float* As = smem;                        // [STAGES][A_STAGE_F], xor-swizzled rows
    float* Xs = smem + STAGES * A_STAGE_F;   // [STAGES][X_STAGE_F]
    const uint32_t As_base = cvta_s(As);
    const uint32_t Xs_base = cvta_s(Xs);

    const int tid  = threadIdx.x;
    const int warp = tid >> 5;
    const int lane = tid & 31;

    const int b  = blockIdx.y;
    const int n0 = blockIdx.x * BM;

    const float* Ab = a + ((size_t)b * Nn + n0) * (size_t)Kk;
    const float* Xb = g_xperm + (size_t)b * (Kk / BK) * X_STAGE_F;

    // A cp.async: 64x32 = 512 chunks of 16B -> 4 per thread
    const float* a_src[4]; uint32_t a_off[4];
#pragma unroll
    for (int i = 0; i < 4; i++) {
        int idx = i * THREADS + tid;
        int row = idx >> 3, c4 = idx & 7;
        a_src[i] = Ab + (size_t)row * Kk + c4 * 4;
        a_off[i] = (uint32_t)((row * BK + ((c4 ^ (row & 7)) << 2)) * 4);
    }
    // X cp.async: 256 contiguous 16B chunks -> 2 per thread
    const float* x_src0 = Xb + tid * 4;
    const float* x_src1 = Xb + (128 + tid) * 4;
    const uint32_t x_off0 = (uint32_t)(tid * 16);
    const uint32_t x_off1 = (uint32_t)((128 + tid) * 16);

    float acc[4][4];
#pragma unroll
    for (int i = 0; i < 4; i++)
#pragma unroll
        for (int j = 0; j < 4; j++) acc[i][j] = 0.f;

    const int lm_row = (lane & 7) + (((lane >> 3) & 1) << 3);
    const int lm_g   = lane >> 4;
    const int a_row  = warp * 16 + lm_row;
    const uint32_t a_row_off = (uint32_t)(a_row * BK * 4);
    const int a_sw  = a_row & 7;

    const int tig = lane & 3;
    const int gid = lane >> 2;
    const int sx  = (lane >> 2) & 1;
    const uint32_t xA = (uint32_t)(lane * 32 + sx * 16);
    const uint32_t xB = (uint32_t)(lane * 32 + (16 ^ (sx * 16)));

#define ISSUE_LOADS(it_, buf_)                                                 \
    do {                                                                       \
        uint32_t abase_ = As_base + (buf_) * A_STAGE_B;                        \
        uint32_t xbase_ = Xs_base + (buf_) * X_STAGE_B;                        \
        _Pragma("unroll")                                                      \
        for (int i_ = 0; i_ < 4; i_++)                                         \
            cp16(abase_ + a_off[i_], a_src[i_] + (it_) * BK);                  \
        cp16(xbase_ + x_off0, x_src0 + (it_) * X_STAGE_F);                     \
        cp16(xbase_ + x_off1, x_src1 + (it_) * X_STAGE_F);                     \
        cp_commit();                                                           \
    } while (0)

#pragma unroll
    for (int s = 0; s < STAGES - 1; ++s) ISSUE_LOADS(s, s);

    int cur = 0;
#pragma unroll 1
    for (int it = 0; it < NIT; ++it) {
        asm volatile("cp.async.wait_group %0;\n" :: "n"(STAGES - 2) : "memory");
        __syncthreads();

        const int nxt = it + STAGES - 1;
        if (nxt < NIT) {
            int nbuf = cur == 0 ? STAGES - 1 : cur - 1;
            ISSUE_LOADS(nxt, nbuf);
        } else {
            cp_commit();
        }

        const uint32_t a_cur = As_base + cur * A_STAGE_B + a_row_off;
        const uint32_t x_cur = Xs_base + cur * X_STAGE_B;

#pragma unroll
        for (int ks = 0; ks < 4; ++ks) {
            uint32_t ar[4];
            {
                int col4 = (ks * 2 + lm_g) ^ a_sw;
                asm volatile(
                    "ldmatrix.sync.aligned.m8n8.x4.shared.b16 {%0,%1,%2,%3}, [%4];\n"
                    : "=r"(ar[0]), "=r"(ar[1]), "=r"(ar[2]), "=r"(ar[3])
                    : "r"(a_cur + col4 * 16));
            }
            uint32_t at[4];
#pragma unroll
            for (int j = 0; j < 4; j++)
                asm("cvt.rna.tf32.f32 %0, %1;" : "=r"(at[j]) : "f"(__uint_as_float(ar[j])));

            uint32_t fr[8];
            {
                uint32_t base = x_cur + ks * 1024;
                asm volatile("ld.shared.v4.b32 {%0,%1,%2,%3}, [%4];\n"
                    : "=r"(fr[0]), "=r"(fr[1]), "=r"(fr[2]), "=r"(fr[3])
                    : "r"(base + xA));
                asm volatile("ld.shared.v4.b32 {%0,%1,%2,%3}, [%4];\n"
                    : "=r"(fr[4]), "=r"(fr[5]), "=r"(fr[6]), "=r"(fr[7])
                    : "r"(base + xB));
            }
#pragma unroll
            for (int ni = 0; ni < 4; ++ni)
                MMA_TF32(acc[ni], at[0], at[1], at[2], at[3], fr[2 * ni], fr[2 * ni + 1]);
        }
        cur = cur + 1 < STAGES ? cur + 1 : 0;
    }

    // ---- epilogue: direct stores ----
    const int orow = n0 + warp * 16 + gid;
    float* ob = out + (size_t)b * Nn * Dd;
#pragma unroll
    for (int ni = 0; ni < 4; ++ni) {
        int col = ni * 8 + tig * 2;
        *reinterpret_cast<float2*>(&ob[(size_t)orow * Dd + col]) =
            make_float2(acc[ni][0], acc[ni][1]);
        *reinterpret_cast<float2*>(&ob[(size_t)(orow + 8) * Dd + col]) =
            make_float2(acc[ni][2], acc[ni][3]);
    }
}

extern "C" void kernel_launch(void* const* d_in, const int* in_sizes, int n_in,
                              void* d_out, int out_size)
{
    const float* x;
    const float* a;
    if (in_sizes[0] < in_sizes[1]) {
        x = (const float*)d_in[0];
        a = (const float*)d_in[1];
    } else {
        x = (const float*)d_in[1];
        a = (const float*)d_in[0];
    }
    float* out = (float*)d_out;

    permute_x_kernel<<<(Bsz * Kk * Dd) / 256, 256>>>(x);

    cudaFuncSetAttribute(gsum_tf32_kernel,
                         cudaFuncAttributeMaxDynamicSharedMemorySize, SMEM_BYTES);
    dim3 grid(Nn / BM, Bsz);
    gsum_tf32_kernel<<<grid, THREADS, SMEM_BYTES>>>(a, out);
}

// round 5
// speedup vs baseline: 1.4077x; 1.4077x over previous
#include <cuda_runtime.h>
#include <cstdint>

// out[b] = a[b] @ x[b] : a [8,4096,4096] f32, x [8,4096,32] f32, out [8,4096,32] f32
// Round 5: round-2 wave shape (4 CTAs/SM, single wave) + pre-permuted X (LDS.128 B path,
// tile-staged fast permute) + 4-stage cp.async pipeline.

#define DEV __device__ __forceinline__

constexpr int Bsz = 8;
constexpr int Nn  = 4096;
constexpr int Dd  = 32;
constexpr int Kk  = 4096;

constexpr int BM  = 64;
constexpr int BK  = 32;
constexpr int NIT = Kk / BK;   // 128
constexpr int THREADS = 128;
constexpr int STAGES = 4;

constexpr int A_STAGE_F = BM * BK;       // 2048 floats
constexpr int X_STAGE_F = BK * Dd;       // 1024 floats
constexpr int A_STAGE_B = A_STAGE_F * 4; // 8192 B
constexpr int X_STAGE_B = X_STAGE_F * 4; // 4096 B
constexpr int SMEM_BYTES = STAGES * (A_STAGE_B + X_STAGE_B); // 49152 B -> 4 CTAs/SM

// Permuted, tf32-rounded X: [b][kb(128)][ks(4)][lane(32)][8 floats], bank-swizzled.
__device__ float g_xperm[Bsz * (Kk / BK) * X_STAGE_F];

DEV uint32_t cvta_s(const void* p) { return (uint32_t)__cvta_generic_to_shared(p); }
DEV void cp16(uint32_t dst, const void* src) {
    asm volatile("cp.async.cg.shared.global [%0], [%1], 16;\n" :: "r"(dst), "l"(src));
}
DEV void cp_commit() { asm volatile("cp.async.commit_group;\n" ::: "memory"); }

#define MMA_TF32(C, A0, A1, A2, A3, B0, B1)                                    \
    asm volatile(                                                              \
        "mma.sync.aligned.m16n8k8.row.col.f32.tf32.tf32.f32 "                  \
        "{%0,%1,%2,%3}, {%4,%5,%6,%7}, {%8,%9}, {%0,%1,%2,%3};\n"              \
        : "+f"(C[0]), "+f"(C[1]), "+f"(C[2]), "+f"(C[3])                       \
        : "r"(A0), "r"(A1), "r"(A2), "r"(A3), "r"(B0), "r"(B1))

// ---------------- tile-staged permute + rna-round X ----------------
// Permutation is closed within each 32x32 (k,d) tile of 1024 floats.
// One block per tile: coalesced load -> smem -> coalesced store (permuted smem read).
__global__ void permute_x_kernel(const float* __restrict__ x) {
    __shared__ float tile[BK * Dd];
    const int t = blockIdx.x;                     // b*128 + kb
    const float* src = x + (size_t)t * (BK * Dd); // contiguous 1024-float tile
    float* dst = g_xperm + (size_t)t * X_STAGE_F;

#pragma unroll
    for (int i = threadIdx.x; i < BK * Dd; i += 256) tile[i] = src[i];
    __syncthreads();

#pragma unroll
    for (int i = threadIdx.x; i < X_STAGE_F; i += 256) {
        int w    = i & 3;
        int c    = (i >> 2) & 1;
        int lane = (i >> 3) & 31;
        int ks   = i >> 8;
        int s = (lane >> 2) & 1;
        int j = (c ^ s) * 4 + w;
        int tig = lane & 3, gid = lane >> 2;
        int kr = ks * 8 + tig + 4 * (j & 1);
        int d  = (j >> 1) * 8 + gid;
        uint32_t tt;
        asm("cvt.rna.tf32.f32 %0, %1;" : "=r"(tt) : "f"(tile[kr * Dd + d]));
        dst[i] = __uint_as_float(tt);
    }
}

// ---------------- main GEMM ----------------
__global__ __launch_bounds__(THREADS)
void gsum_tf32_kernel(const float* __restrict__ a, float* __restrict__ out)
{
    extern __shared__ float smem[];
    float* As = smem;                        // [STAGES][A_STAGE_F], xor-swizzled rows
    float* Xs = smem + STAGES * A_STAGE_F;   // [STAGES][X_STAGE_F]
    const uint32_t As_base = cvta_s(As);
    const uint32_t Xs_base = cvta_s(Xs);

    const int tid  = threadIdx.x;
    const int warp = tid >> 5;
    const int lane = tid & 31;

    const int b  = blockIdx.y;
    const int n0 = blockIdx.x * BM;

    const float* Ab = a + ((size_t)b * Nn + n0) * (size_t)Kk;
    const float* Xb = g_xperm + (size_t)b * (Kk / BK) * X_STAGE_F;

    // A cp.async: 64x32 = 512 chunks of 16B -> 4 per thread
    const float* a_src[4]; uint32_t a_off[4];
#pragma unroll
    for (int i = 0; i < 4; i++) {
        int idx = i * THREADS + tid;
        int row = idx >> 3, c4 = idx & 7;
        a_src[i] = Ab + (size_t)row * Kk + c4 * 4;
        a_off[i] = (uint32_t)((row * BK + ((c4 ^ (row & 7)) << 2)) * 4);
    }
    // X cp.async: 256 contiguous 16B chunks -> 2 per thread
    const float* x_src0 = Xb + tid * 4;
    const float* x_src1 = Xb + (128 + tid) * 4;
    const uint32_t x_off0 = (uint32_t)(tid * 16);
    const uint32_t x_off1 = (uint32_t)((128 + tid) * 16);

    float acc[4][4];
#pragma unroll
    for (int i = 0; i < 4; i++)
#pragma unroll
        for (int j = 0; j < 4; j++) acc[i][j] = 0.f;

    const int lm_row = (lane & 7) + (((lane >> 3) & 1) << 3);
    const int lm_g   = lane >> 4;
    const int a_row  = warp * 16 + lm_row;
    const uint32_t a_row_off = (uint32_t)(a_row * BK * 4);
    const int a_sw  = a_row & 7;

    const int tig = lane & 3;
    const int gid = lane >> 2;
    const int sx  = (lane >> 2) & 1;
    const uint32_t xA = (uint32_t)(lane * 32 + sx * 16);
    const uint32_t xB = (uint32_t)(lane * 32 + (16 ^ (sx * 16)));

#define ISSUE_LOADS(it_, buf_)                                                 \
    do {                                                                       \
        uint32_t abase_ = As_base + (buf_) * A_STAGE_B;                        \
        uint32_t xbase_ = Xs_base + (buf_) * X_STAGE_B;                        \
        _Pragma("unroll")                                                      \
        for (int i_ = 0; i_ < 4; i_++)                                         \
            cp16(abase_ + a_off[i_], a_src[i_] + (it_) * BK);                  \
        cp16(xbase_ + x_off0, x_src0 + (it_) * X_STAGE_F);                     \
        cp16(xbase_ + x_off1, x_src1 + (it_) * X_STAGE_F);                     \
        cp_commit();                                                           \
    } while (0)

#pragma unroll
    for (int s = 0; s < STAGES - 1; ++s) ISSUE_LOADS(s, s);

    int cur = 0;
#pragma unroll 1
    for (int it = 0; it < NIT; ++it) {
        asm volatile("cp.async.wait_group %0;\n" :: "n"(STAGES - 2) : "memory");
        __syncthreads();

        const int nxt = it + STAGES - 1;
        if (nxt < NIT) {
            int nbuf = cur == 0 ? STAGES - 1 : cur - 1;
            ISSUE_LOADS(nxt, nbuf);
        } else {
            cp_commit();
        }

        const uint32_t a_cur = As_base + cur * A_STAGE_B + a_row_off;
        const uint32_t x_cur = Xs_base + cur * X_STAGE_B;

#pragma unroll
        for (int ks = 0; ks < 4; ++ks) {
            uint32_t ar[4];
            {
                int col4 = (ks * 2 + lm_g) ^ a_sw;
                asm volatile(
                    "ldmatrix.sync.aligned.m8n8.x4.shared.b16 {%0,%1,%2,%3}, [%4];\n"
                    : "=r"(ar[0]), "=r"(ar[1]), "=r"(ar[2]), "=r"(ar[3])
                    : "r"(a_cur + col4 * 16));
            }
            uint32_t at[4];
#pragma unroll
            for (int j = 0; j < 4; j++)
                asm("cvt.rna.tf32.f32 %0, %1;" : "=r"(at[j]) : "f"(__uint_as_float(ar[j])));

            uint32_t fr[8];
            {
                uint32_t base = x_cur + ks * 1024;
                asm volatile("ld.shared.v4.b32 {%0,%1,%2,%3}, [%4];\n"
                    : "=r"(fr[0]), "=r"(fr[1]), "=r"(fr[2]), "=r"(fr[3])
                    : "r"(base + xA));
                asm volatile("ld.shared.v4.b32 {%0,%1,%2,%3}, [%4];\n"
                    : "=r"(fr[4]), "=r"(fr[5]), "=r"(fr[6]), "=r"(fr[7])
                    : "r"(base + xB));
            }
#pragma unroll
            for (int ni = 0; ni < 4; ++ni)
                MMA_TF32(acc[ni], at[0], at[1], at[2], at[3], fr[2 * ni], fr[2 * ni + 1]);
        }
        cur = cur + 1 < STAGES ? cur + 1 : 0;
    }

    // ---- epilogue: direct stores ----
    const int orow = n0 + warp * 16 + gid;
    float* ob = out + (size_t)b * Nn * Dd;
#pragma unroll
    for (int ni = 0; ni < 4; ++ni) {
        int col = ni * 8 + tig * 2;
        *reinterpret_cast<float2*>(&ob[(size_t)orow * Dd + col]) =
            make_float2(acc[ni][0], acc[ni][1]);
        *reinterpret_cast<float2*>(&ob[(size_t)(orow + 8) * Dd + col]) =
            make_float2(acc[ni][2], acc[ni][3]);
    }
}

extern "C" void kernel_launch(void* const* d_in, const int* in_sizes, int n_in,
                              void* d_out, int out_size)
{
    const float* x;
    const float* a;
    if (in_sizes[0] < in_sizes[1]) {
        x = (const float*)d_in[0];
        a = (const float*)d_in[1];
    } else {
        x = (const float*)d_in[1];
        a = (const float*)d_in[0];
    }
    float* out = (float*)d_out;

    permute_x_kernel<<<Bsz * (Kk / BK), 256>>>(x);

    cudaFuncSetAttribute(gsum_tf32_kernel,
                         cudaFuncAttributeMaxDynamicSharedMemorySize, SMEM_BYTES);
    dim3 grid(Nn / BM, Bsz);
    gsum_tf32_kernel<<<grid, THREADS, SMEM_BYTES>>>(a, out);
}